// round 14
// baseline (speedup 1.0000x reference)
#include <cuda_runtime.h>
#include <cuda_fp16.h>
#include <stdint.h>
#include <math.h>

// Problem constants
#define BATCH 2
#define SEQ   2048
#define DIM   1024
#define HEADS 16
#define HD    64
#define MTOK  (BATCH * SEQ)            // 4096 tokens
#define HALF  (DIM / 2)                // 512

// fp16 GEMM tiling: CTA 128x256, 8 warps (2Mx4N), warp tile 64x64,
// K-chunk 32 halves (64B rows + 16B pad), 4 stages.
#define GM 128
#define GN 256
#define GKC 32
#define NCHUNK (DIM / GKC)             // 32
#define NSTAGE 4
#define RSTRIDE 80                      // 32 halves (64B) + 16B pad
#define RA  0
#define RBH (128 * RSTRIDE)             // 10240
#define RBL (RBH + 256 * RSTRIDE)       // 30720
#define STAGE_BYTES (RBL + 256 * RSTRIDE) // 51200
#define SMEM_TOTAL (NSTAGE * STAGE_BYTES) // 204800 (< 227KB limit)

// ---------------------------------------------------------------------------
// Device scratch (no cudaMalloc allowed)
// ---------------------------------------------------------------------------
__device__ float g_q[MTOK * DIM];
__device__ float g_k[MTOK * DIM];
__device__ float g_v[MTOK * DIM];
__device__ float g_cos[SEQ * HALF];
__device__ float g_sin[SEQ * HALF];

__device__ __half g_ah[MTOK * DIM];      // fp16(inputs)
__device__ __half g_ch[MTOK * DIM];      // fp16(context)
__device__ __half g_xh[MTOK * DIM];      // fp16(scrambled ctx)

__device__ __half g_wq_h[DIM * DIM], g_wq_l[DIM * DIM];  // transposed [N][K]
__device__ __half g_wk_h[DIM * DIM], g_wk_l[DIM * DIM];
__device__ __half g_wv_h[DIM * DIM], g_wv_l[DIM * DIM];
__device__ __half g_wo_h[DIM * DIM], g_wo_l[DIM * DIM];

// ---------------------------------------------------------------------------
// Helpers
// ---------------------------------------------------------------------------
__device__ __forceinline__ uint32_t smem_u32(const void* p) {
    uint32_t a;
    asm("{ .reg .u64 t; cvta.to.shared.u64 t, %1; cvt.u32.u64 %0, t; }"
        : "=r"(a) : "l"(p));
    return a;
}

__device__ __forceinline__ void cp16(uint32_t smem, const void* g) {
    asm volatile("cp.async.cg.shared.global [%0], [%1], 16;" :: "r"(smem), "l"(g));
}
__device__ __forceinline__ void cp_commit() {
    asm volatile("cp.async.commit_group;" ::: "memory");
}
template <int N>
__device__ __forceinline__ void cp_wait() {
    asm volatile("cp.async.wait_group %0;" :: "n"(N) : "memory");
}

__device__ __forceinline__ uint32_t lds_u32(uint32_t addr) {
    uint32_t v;
    asm volatile("ld.shared.b32 %0, [%1];" : "=r"(v) : "r"(addr));
    return v;
}

// fp16 mma, fp32 accumulate: m16n8k16
__device__ __forceinline__ void mma_f16(float* d, const uint32_t* a,
                                        uint32_t b0, uint32_t b1) {
    asm volatile(
        "mma.sync.aligned.m16n8k16.row.col.f32.f16.f16.f32 "
        "{%0,%1,%2,%3}, {%4,%5,%6,%7}, {%8,%9}, {%0,%1,%2,%3};"
        : "+f"(d[0]), "+f"(d[1]), "+f"(d[2]), "+f"(d[3])
        : "r"(a[0]), "r"(a[1]), "r"(a[2]), "r"(a[3]), "r"(b0), "r"(b1));
}

// ---------------------------------------------------------------------------
// RoPE tables — fp32 throughout.
// ---------------------------------------------------------------------------
__global__ void rope_tab_kernel() {
    int idx = blockIdx.x * 256 + threadIdx.x;
    int s = idx >> 9;
    int j = idx & (HALF - 1);
    float inv = exp2f((float)j * -0.025952563241303614f);  // 2*log2(1e4)/1024
    float arg = (float)s * inv;
    float sn, cs;
    sincosf(arg, &sn, &cs);
    g_cos[idx] = cs;
    g_sin[idx] = sn;
}

// ---------------------------------------------------------------------------
// Activations: fp32 -> fp16, same layout.
// ---------------------------------------------------------------------------
__global__ void act_half_kernel(const float* __restrict__ X,
                                __half* __restrict__ Y) {
    int i = (blockIdx.x * 256 + threadIdx.x) * 4;
    float4 x = *(const float4*)(X + i);
    *(__half2*)(Y + i)     = __floats2half2_rn(x.x, x.y);
    *(__half2*)(Y + i + 2) = __floats2half2_rn(x.z, x.w);
}

// ---------------------------------------------------------------------------
// Weight transposes: W [K][N] fp32 -> transposed [N][K] fp16 hi + fp16 lo.
// blockIdx.z selects the matrix.
// ---------------------------------------------------------------------------
__global__ void convert_w4_kernel(const float* __restrict__ W0,
                                  const float* __restrict__ W1,
                                  const float* __restrict__ W2,
                                  const float* __restrict__ W3) {
    __shared__ float t[32][33];
    const float* W = (blockIdx.z == 0) ? W0 : (blockIdx.z == 1) ? W1
                   : (blockIdx.z == 2) ? W2 : W3;
    __half* Th = (blockIdx.z == 0) ? g_wq_h : (blockIdx.z == 1) ? g_wk_h
               : (blockIdx.z == 2) ? g_wv_h : g_wo_h;
    __half* Tl = (blockIdx.z == 0) ? g_wq_l : (blockIdx.z == 1) ? g_wk_l
               : (blockIdx.z == 2) ? g_wv_l : g_wo_l;
    int k0 = blockIdx.y * 32, n0 = blockIdx.x * 32;
    int tx = threadIdx.x, ty = threadIdx.y;   // 32 x 8
#pragma unroll
    for (int i = 0; i < 32; i += 8)
        t[ty + i][tx] = W[(size_t)(k0 + ty + i) * DIM + n0 + tx];
    __syncthreads();
#pragma unroll
    for (int i = 0; i < 32; i += 8) {
        float x = t[tx][ty + i];              // W[k0+tx][n0+ty+i]
        __half h = __float2half_rn(x);
        __half l = __float2half_rn(x - __half2float(h));
        size_t o = (size_t)(n0 + ty + i) * DIM + k0 + tx;
        Th[o] = h;
        Tl[o] = l;
    }
}

// ---------------------------------------------------------------------------
// fp16 2-product GEMM:  C[M,N] = A @ (Bh + Bl)^T + bias
// A fp16 [m][k] K-major; B hi/lo fp16 [n][k] K-major (pre-transposed W).
// CTA 128x256, 8 warps (2Mx4N), warp tile 64x64, K-chunk 32 halves, 4 stages,
// single barrier per chunk, register double-buffered fragments.
// Per k16 step: 32 hi-product + 32 lo-product m16n8k16 MMAs.
// ---------------------------------------------------------------------------
__device__ __forceinline__ void gemm_body(
    const __half* __restrict__ A, const __half* __restrict__ Bh,
    const __half* __restrict__ Bl,
    const float* __restrict__ bias, float* __restrict__ C,
    char* smem, int row0, int col0) {
    const int tid  = threadIdx.x;
    const int wid  = tid >> 5;
    const int lane = tid & 31;
    const uint32_t sb = smem_u32(smem);

    const int wm = wid >> 2;            // 0..1
    const int wn = wid & 3;             // 0..3
    const int m_base = wm * 64;
    const int n_base = wn * 64;

    float acc[4][8][4];
#pragma unroll
    for (int i = 0; i < 4; i++)
#pragma unroll
        for (int j = 0; j < 8; j++)
#pragma unroll
            for (int e = 0; e < 4; e++) acc[i][j][e] = 0.0f;

    auto issue = [&](int c) {
        const uint32_t st = sb + (uint32_t)(c & (NSTAGE - 1)) * STAGE_BYTES;
        const int k0 = c * GKC;
        // A: 128 rows x 4 segs (16B = 8 halves) = 512 segs
#pragma unroll
        for (int i = 0; i < 2; i++) {
            int seg = tid + i * 256;
            int r  = seg >> 2;
            int s8 = seg & 3;
            cp16(st + RA + r * RSTRIDE + s8 * 16,
                 A + (size_t)(row0 + r) * DIM + k0 + s8 * 8);
        }
        // B hi/lo: 256 rows x 4 segs each
#pragma unroll
        for (int i = 0; i < 4; i++) {
            int seg = tid + i * 256;
            int r  = seg >> 2;
            int s8 = seg & 3;
            size_t src = (size_t)(col0 + r) * DIM + k0 + s8 * 8;
            cp16(st + RBH + r * RSTRIDE + s8 * 16, Bh + src);
            cp16(st + RBL + r * RSTRIDE + s8 * 16, Bl + src);
        }
        cp_commit();
    };

    issue(0); issue(1); issue(2);

    for (int c = 0; c < NCHUNK; c++) {
        cp_wait<2>();
        __syncthreads();
        // stage (c+3)%4 == (c-1)%4: all readers passed the barrier above.
        if (c + 3 < NCHUNK) issue(c + 3);

        const uint32_t st = sb + (uint32_t)(c & (NSTAGE - 1)) * STAGE_BYTES;
        const uint32_t abase  = st + RA  + (m_base + (lane >> 2)) * RSTRIDE + (lane & 3) * 4;
        const uint32_t bhbase = st + RBH + (n_base + (lane >> 2)) * RSTRIDE + (lane & 3) * 4;
        const uint32_t blbase = st + RBL + (n_base + (lane >> 2)) * RSTRIDE + (lane & 3) * 4;

        uint32_t af[2][4][4], bh[2][8][2], bl[2][8][2];

        auto load_frags = [&](int ks, int buf) {
            const int kb = ks * 32;     // k16 step = 16 halves = 32 bytes
#pragma unroll
            for (int mi = 0; mi < 4; mi++) {
                uint32_t base = abase + mi * (16 * RSTRIDE) + kb;
                af[buf][mi][0] = lds_u32(base);
                af[buf][mi][1] = lds_u32(base + 8 * RSTRIDE);
                af[buf][mi][2] = lds_u32(base + 16);
                af[buf][mi][3] = lds_u32(base + 8 * RSTRIDE + 16);
            }
#pragma unroll
            for (int nj = 0; nj < 8; nj++) {
                uint32_t bh_b = bhbase + nj * (8 * RSTRIDE) + kb;
                uint32_t bl_b = blbase + nj * (8 * RSTRIDE) + kb;
                bh[buf][nj][0] = lds_u32(bh_b);
                bh[buf][nj][1] = lds_u32(bh_b + 16);
                bl[buf][nj][0] = lds_u32(bl_b);
                bl[buf][nj][1] = lds_u32(bl_b + 16);
            }
        };

        load_frags(0, 0);
#pragma unroll
        for (int ks = 0; ks < 2; ks++) {
            if (ks < 1) load_frags(ks + 1, (ks + 1) & 1);
            const int cb = ks & 1;
            // hi product (32 MMAs), then lo product (32 MMAs)
#pragma unroll
            for (int mi = 0; mi < 4; mi++)
#pragma unroll
                for (int nj = 0; nj < 8; nj++)
                    mma_f16(acc[mi][nj], af[cb][mi], bh[cb][nj][0], bh[cb][nj][1]);
#pragma unroll
            for (int mi = 0; mi < 4; mi++)
#pragma unroll
                for (int nj = 0; nj < 8; nj++)
                    mma_f16(acc[mi][nj], af[cb][mi], bl[cb][nj][0], bl[cb][nj][1]);
        }
    }

    // Epilogue: add bias, store fp32
    const int rw = row0 + m_base;
    const int cw = col0 + n_base;
#pragma unroll
    for (int nj = 0; nj < 8; nj++) {
        int n = cw + nj * 8 + (lane & 3) * 2;
        float bx = __ldg(&bias[n]);
        float by = __ldg(&bias[n + 1]);
#pragma unroll
        for (int mi = 0; mi < 4; mi++) {
            int r = rw + mi * 16 + (lane >> 2);
            float2 v0 = make_float2(acc[mi][nj][0] + bx, acc[mi][nj][1] + by);
            float2 v1 = make_float2(acc[mi][nj][2] + bx, acc[mi][nj][3] + by);
            *(float2*)(C + (size_t)r * DIM + n)       = v0;
            *(float2*)(C + (size_t)(r + 8) * DIM + n) = v1;
        }
    }
}

// Fused Q/K/V projections: blockIdx.z selects {A, W, bias, C}.
__global__ void __launch_bounds__(256, 1)
gemm_qkv(const float* __restrict__ bq, const float* __restrict__ bk,
         const float* __restrict__ bv) {
    extern __shared__ __align__(1024) char smem[];
    int z = blockIdx.z;
    const __half* A  = (z == 0) ? g_ah : g_ch;
    const __half* Bh = (z == 0) ? g_wq_h : (z == 1) ? g_wk_h : g_wv_h;
    const __half* Bl = (z == 0) ? g_wq_l : (z == 1) ? g_wk_l : g_wv_l;
    const float* bias = (z == 0) ? bq : (z == 1) ? bk : bv;
    float* C          = (z == 0) ? g_q : (z == 1) ? g_k : g_v;
    gemm_body(A, Bh, Bl, bias, C, smem, blockIdx.y * GM, blockIdx.x * GN);
}

// O projection.
__global__ void __launch_bounds__(256, 1)
gemm_o(const float* __restrict__ bo, float* __restrict__ out) {
    extern __shared__ __align__(1024) char smem[];
    gemm_body(g_xh, g_wo_h, g_wo_l, bo, out, smem,
              blockIdx.y * GM, blockIdx.x * GN);
}

// ---------------------------------------------------------------------------
// Per-token attention: RoPE from global, padded qr/kr, shfl softmax,
// scrambled ctx stored as fp16 for the O projection.
// Scramble: ctx[b,s,h,e] -> row h*128 + s/16, col (s%16)*64 + e
// ---------------------------------------------------------------------------
#define QKPAD 66

__global__ __launch_bounds__(256)
void attn_kernel(float* __restrict__ attn_out, int write_attn) {
    __shared__ float v[DIM];
    __shared__ float qr[HEADS * QKPAD], kr[HEADS * QKPAD];
    __shared__ float sc[256];

    int t   = blockIdx.x;
    int b   = t >> 11;
    int s   = t & (SEQ - 1);
    int tid = threadIdx.x;
    int d   = tid * 4;

    ((float4*)v)[tid] = ((const float4*)(g_v + (size_t)t * DIM))[tid];

    // RoPE directly from global q/k
    {
        int j  = d & (HALF - 1);
        int pd = (d < HALF) ? d + HALF : d - HALF;
        float sgn = (d < HALF) ? -1.0f : 1.0f;
        float4 c4 = *(const float4*)(g_cos + (size_t)s * HALF + j);
        float4 s4 = *(const float4*)(g_sin + (size_t)s * HALF + j);
        const float* qg = g_q + (size_t)t * DIM;
        const float* kg = g_k + (size_t)t * DIM;
        float4 qv = *(const float4*)(qg + d),  qp = *(const float4*)(qg + pd);
        float4 kv = *(const float4*)(kg + d),  kp = *(const float4*)(kg + pd);
        int row = d >> 6, e = d & 63;
        float* qd = qr + row * QKPAD + e;
        float* kd = kr + row * QKPAD + e;
        qd[0] = qv.x * c4.x + sgn * qp.x * s4.x;
        qd[1] = qv.y * c4.y + sgn * qp.y * s4.y;
        qd[2] = qv.z * c4.z + sgn * qp.z * s4.z;
        qd[3] = qv.w * c4.w + sgn * qp.w * s4.w;
        kd[0] = kv.x * c4.x + sgn * kp.x * s4.x;
        kd[1] = kv.y * c4.y + sgn * kp.y * s4.y;
        kd[2] = kv.z * c4.z + sgn * kp.z * s4.z;
        kd[3] = kv.w * c4.w + sgn * kp.w * s4.w;
    }
    __syncthreads();

    // Scores + softmax, one thread per (i,j)
    {
        int i = tid >> 4, j = tid & 15;
        const float* qp = qr + i * QKPAD;
        const float* kp = kr + j * QKPAD;
        float sum = 0.0f;
#pragma unroll
        for (int e = 0; e < HD; e++) sum += qp[e] * kp[e];
        sum *= 0.125f;
        float m = sum;
#pragma unroll
        for (int off = 8; off > 0; off >>= 1)
            m = fmaxf(m, __shfl_xor_sync(0xFFFFFFFFu, m, off, 16));
        float ex = expf(sum - m);
        float tot = ex;
#pragma unroll
        for (int off = 8; off > 0; off >>= 1)
            tot += __shfl_xor_sync(0xFFFFFFFFu, tot, off, 16);
        float p = ex / tot;
        sc[tid] = p;
        if (write_attn) attn_out[(size_t)t * 256 + tid] = p;
    }
    __syncthreads();

    // ctx + scrambled fp16 store
    {
        int i = d >> 6, e = d & 63;
        float4 acc = make_float4(0.f, 0.f, 0.f, 0.f);
        const float* pr = sc + i * 16;
#pragma unroll
        for (int j = 0; j < HEADS; j++) {
            float p = pr[j];
            float4 vv = *(float4*)(v + j * HD + e);
            acc.x += p * vv.x; acc.y += p * vv.y;
            acc.z += p * vv.z; acc.w += p * vv.w;
        }
        int r = i * (SEQ / HEADS) + (s >> 4);
        int c = ((s & 15) << 6) | e;
        size_t off = (size_t)b * SEQ * DIM + (size_t)r * DIM + c;
        *(__half2*)(g_xh + off)     = __floats2half2_rn(acc.x, acc.y);
        *(__half2*)(g_xh + off + 2) = __floats2half2_rn(acc.z, acc.w);
    }
}

// ---------------------------------------------------------------------------
// Host launcher. Launch #4 == gemm_qkv  <-- ncu capture slot.
// ---------------------------------------------------------------------------
extern "C" void kernel_launch(void* const* d_in, const int* in_sizes, int n_in,
                              void* d_out, int out_size) {
    const float* inputs  = (const float*)d_in[0];
    const float* context = (const float*)d_in[1];
    const float* Wq = (const float*)d_in[2];
    const float* bq = (const float*)d_in[3];
    const float* Wk = (const float*)d_in[4];
    const float* bk = (const float*)d_in[5];
    const float* Wv = (const float*)d_in[6];
    const float* bv = (const float*)d_in[7];
    const float* Wo = (const float*)d_in[8];
    const float* bo = (const float*)d_in[9];
    float* out = (float*)d_out;

    cudaFuncSetAttribute(gemm_qkv, cudaFuncAttributeMaxDynamicSharedMemorySize,
                         SMEM_TOTAL);
    cudaFuncSetAttribute(gemm_o, cudaFuncAttributeMaxDynamicSharedMemorySize,
                         SMEM_TOTAL);

    __half *pah, *pch;
    cudaGetSymbolAddress((void**)&pah, g_ah);
    cudaGetSymbolAddress((void**)&pch, g_ch);

    const int out_elems  = MTOK * DIM;
    const int attn_elems = MTOK * HEADS * HEADS;
    int write_attn = (out_size >= out_elems + attn_elems) ? 1 : 0;
    float* attn_out = out + out_elems;

    // #1: weight transposes + fp16 hi/lo split (one launch)
    convert_w4_kernel<<<dim3(32, 32, 4), dim3(32, 8)>>>(Wq, Wk, Wv, Wo);
    // #2-3: activation fp16 conversion
    act_half_kernel<<<(MTOK * DIM) / 1024, 256>>>(inputs,  pah);
    act_half_kernel<<<(MTOK * DIM) / 1024, 256>>>(context, pch);
    // #4: fused Q/K/V projections  <-- ncu capture slot
    gemm_qkv<<<dim3(DIM / GN, MTOK / GM, 3), 256, SMEM_TOTAL>>>(bq, bk, bv);
    // #5: RoPE tables
    rope_tab_kernel<<<(SEQ * HALF) / 256, 256>>>();
    // #6: RoPE + per-token head attention + scramble (fp16 ctx out)
    attn_kernel<<<MTOK, 256>>>(attn_out, write_attn);
    // #7: O projection
    gemm_o<<<dim3(DIM / GN, MTOK / GM), 256, SMEM_TOTAL>>>(bo, out);
}

// round 15
// speedup vs baseline: 1.5103x; 1.5103x over previous
#include <cuda_runtime.h>
#include <cuda_fp16.h>
#include <stdint.h>
#include <math.h>

// Problem constants
#define BATCH 2
#define SEQ   2048
#define DIM   1024
#define HEADS 16
#define HD    64
#define MTOK  (BATCH * SEQ)            // 4096 tokens
#define HALF  (DIM / 2)                // 512

// fp16 single-product GEMM tiling: CTA 128x256, 8 warps (2Mx4N), warp 64x64,
// K-chunk 32 halves (64B rows + 16B pad), 4 stages.
#define GM 128
#define GN 256
#define GKC 32
#define NCHUNK (DIM / GKC)             // 32
#define NSTAGE 4
#define RSTRIDE 80                      // 32 halves (64B) + 16B pad
#define RA  0
#define RB  (128 * RSTRIDE)             // 10240
#define STAGE_BYTES (RB + 256 * RSTRIDE) // 30720
#define SMEM_TOTAL (NSTAGE * STAGE_BYTES) // 122880

// ---------------------------------------------------------------------------
// Device scratch (no cudaMalloc allowed)
// ---------------------------------------------------------------------------
__device__ float g_q[MTOK * DIM];
__device__ float g_k[MTOK * DIM];
__device__ float g_v[MTOK * DIM];
__device__ float g_cos[SEQ * HALF];
__device__ float g_sin[SEQ * HALF];

__device__ __half g_ah[MTOK * DIM];      // fp16(inputs)
__device__ __half g_ch[MTOK * DIM];      // fp16(context)
__device__ __half g_xh[MTOK * DIM];      // fp16(scrambled ctx)

__device__ __half g_wq[DIM * DIM];       // transposed [N][K] fp16
__device__ __half g_wk[DIM * DIM];
__device__ __half g_wv[DIM * DIM];
__device__ __half g_wo[DIM * DIM];

// ---------------------------------------------------------------------------
// Helpers
// ---------------------------------------------------------------------------
__device__ __forceinline__ uint32_t smem_u32(const void* p) {
    uint32_t a;
    asm("{ .reg .u64 t; cvta.to.shared.u64 t, %1; cvt.u32.u64 %0, t; }"
        : "=r"(a) : "l"(p));
    return a;
}

__device__ __forceinline__ void cp16(uint32_t smem, const void* g) {
    asm volatile("cp.async.cg.shared.global [%0], [%1], 16;" :: "r"(smem), "l"(g));
}
__device__ __forceinline__ void cp_commit() {
    asm volatile("cp.async.commit_group;" ::: "memory");
}
template <int N>
__device__ __forceinline__ void cp_wait() {
    asm volatile("cp.async.wait_group %0;" :: "n"(N) : "memory");
}

__device__ __forceinline__ uint32_t lds_u32(uint32_t addr) {
    uint32_t v;
    asm volatile("ld.shared.b32 %0, [%1];" : "=r"(v) : "r"(addr));
    return v;
}

// fp16 mma, fp32 accumulate: m16n8k16
__device__ __forceinline__ void mma_f16(float* d, const uint32_t* a,
                                        uint32_t b0, uint32_t b1) {
    asm volatile(
        "mma.sync.aligned.m16n8k16.row.col.f32.f16.f16.f32 "
        "{%0,%1,%2,%3}, {%4,%5,%6,%7}, {%8,%9}, {%0,%1,%2,%3};"
        : "+f"(d[0]), "+f"(d[1]), "+f"(d[2]), "+f"(d[3])
        : "r"(a[0]), "r"(a[1]), "r"(a[2]), "r"(a[3]), "r"(b0), "r"(b1));
}

// ---------------------------------------------------------------------------
// RoPE tables — fp32 throughout.
// ---------------------------------------------------------------------------
__global__ void rope_tab_kernel() {
    int idx = blockIdx.x * 256 + threadIdx.x;
    int s = idx >> 9;
    int j = idx & (HALF - 1);
    float inv = exp2f((float)j * -0.025952563241303614f);  // 2*log2(1e4)/1024
    float arg = (float)s * inv;
    float sn, cs;
    sincosf(arg, &sn, &cs);
    g_cos[idx] = cs;
    g_sin[idx] = sn;
}

// ---------------------------------------------------------------------------
// Activations: fp32 -> fp16, same layout.
// ---------------------------------------------------------------------------
__global__ void act_half_kernel(const float* __restrict__ X,
                                __half* __restrict__ Y) {
    int i = (blockIdx.x * 256 + threadIdx.x) * 4;
    float4 x = *(const float4*)(X + i);
    *(__half2*)(Y + i)     = __floats2half2_rn(x.x, x.y);
    *(__half2*)(Y + i + 2) = __floats2half2_rn(x.z, x.w);
}

// ---------------------------------------------------------------------------
// Weight transposes: W [K][N] fp32 -> transposed [N][K] fp16.
// blockIdx.z selects the matrix.
// ---------------------------------------------------------------------------
__global__ void convert_w4_kernel(const float* __restrict__ W0,
                                  const float* __restrict__ W1,
                                  const float* __restrict__ W2,
                                  const float* __restrict__ W3) {
    __shared__ float t[32][33];
    const float* W = (blockIdx.z == 0) ? W0 : (blockIdx.z == 1) ? W1
                   : (blockIdx.z == 2) ? W2 : W3;
    __half* T = (blockIdx.z == 0) ? g_wq : (blockIdx.z == 1) ? g_wk
              : (blockIdx.z == 2) ? g_wv : g_wo;
    int k0 = blockIdx.y * 32, n0 = blockIdx.x * 32;
    int tx = threadIdx.x, ty = threadIdx.y;   // 32 x 8
#pragma unroll
    for (int i = 0; i < 32; i += 8)
        t[ty + i][tx] = W[(size_t)(k0 + ty + i) * DIM + n0 + tx];
    __syncthreads();
#pragma unroll
    for (int i = 0; i < 32; i += 8) {
        float x = t[tx][ty + i];              // W[k0+tx][n0+ty+i]
        T[(size_t)(n0 + ty + i) * DIM + k0 + tx] = __float2half_rn(x);
    }
}

// ---------------------------------------------------------------------------
// fp16 single-product GEMM:  C[M,N] = A @ B^T + bias  (fp32 accumulate)
// A fp16 [m][k]; B fp16 [n][k] (pre-transposed W).
// CTA 128x256, 8 warps (2Mx4N), warp tile 64x64, K-chunk 32 halves, 4 stages,
// single barrier per chunk, register double-buffered fragments.
// Per k16 step: 32 m16n8k16 MMAs -> HALF the MMA count of the tf32 kernel.
// ---------------------------------------------------------------------------
__device__ __forceinline__ void gemm_body(
    const __half* __restrict__ A, const __half* __restrict__ B,
    const float* __restrict__ bias, float* __restrict__ C,
    char* smem, int row0, int col0) {
    const int tid  = threadIdx.x;
    const int wid  = tid >> 5;
    const int lane = tid & 31;
    const uint32_t sb = smem_u32(smem);

    const int wm = wid >> 2;            // 0..1
    const int wn = wid & 3;             // 0..3
    const int m_base = wm * 64;
    const int n_base = wn * 64;

    float acc[4][8][4];
#pragma unroll
    for (int i = 0; i < 4; i++)
#pragma unroll
        for (int j = 0; j < 8; j++)
#pragma unroll
            for (int e = 0; e < 4; e++) acc[i][j][e] = 0.0f;

    auto issue = [&](int c) {
        const uint32_t st = sb + (uint32_t)(c & (NSTAGE - 1)) * STAGE_BYTES;
        const int k0 = c * GKC;
        // A: 128 rows x 4 segs (16B = 8 halves)
#pragma unroll
        for (int i = 0; i < 2; i++) {
            int seg = tid + i * 256;
            int r  = seg >> 2;
            int s8 = seg & 3;
            cp16(st + RA + r * RSTRIDE + s8 * 16,
                 A + (size_t)(row0 + r) * DIM + k0 + s8 * 8);
        }
        // B: 256 rows x 4 segs
#pragma unroll
        for (int i = 0; i < 4; i++) {
            int seg = tid + i * 256;
            int r  = seg >> 2;
            int s8 = seg & 3;
            cp16(st + RB + r * RSTRIDE + s8 * 16,
                 B + (size_t)(col0 + r) * DIM + k0 + s8 * 8);
        }
        cp_commit();
    };

    issue(0); issue(1); issue(2);

    for (int c = 0; c < NCHUNK; c++) {
        cp_wait<2>();
        __syncthreads();
        // stage (c+3)%4 == (c-1)%4: all readers passed the barrier above.
        if (c + 3 < NCHUNK) issue(c + 3);

        const uint32_t st = sb + (uint32_t)(c & (NSTAGE - 1)) * STAGE_BYTES;
        const uint32_t abase = st + RA + (m_base + (lane >> 2)) * RSTRIDE + (lane & 3) * 4;
        const uint32_t bbase = st + RB + (n_base + (lane >> 2)) * RSTRIDE + (lane & 3) * 4;

        uint32_t af[2][4][4], bf[2][8][2];

        auto load_frags = [&](int ks, int buf) {
            const int kb = ks * 32;     // k16 step = 16 halves = 32 bytes
#pragma unroll
            for (int mi = 0; mi < 4; mi++) {
                uint32_t base = abase + mi * (16 * RSTRIDE) + kb;
                af[buf][mi][0] = lds_u32(base);
                af[buf][mi][1] = lds_u32(base + 8 * RSTRIDE);
                af[buf][mi][2] = lds_u32(base + 16);
                af[buf][mi][3] = lds_u32(base + 8 * RSTRIDE + 16);
            }
#pragma unroll
            for (int nj = 0; nj < 8; nj++) {
                uint32_t base = bbase + nj * (8 * RSTRIDE) + kb;
                bf[buf][nj][0] = lds_u32(base);
                bf[buf][nj][1] = lds_u32(base + 16);
            }
        };

        load_frags(0, 0);
#pragma unroll
        for (int ks = 0; ks < 2; ks++) {
            if (ks < 1) load_frags(ks + 1, (ks + 1) & 1);
            const int cb = ks & 1;
#pragma unroll
            for (int mi = 0; mi < 4; mi++)
#pragma unroll
                for (int nj = 0; nj < 8; nj++)
                    mma_f16(acc[mi][nj], af[cb][mi], bf[cb][nj][0], bf[cb][nj][1]);
        }
    }

    // Epilogue: add bias, store fp32
    const int rw = row0 + m_base;
    const int cw = col0 + n_base;
#pragma unroll
    for (int nj = 0; nj < 8; nj++) {
        int n = cw + nj * 8 + (lane & 3) * 2;
        float bx = __ldg(&bias[n]);
        float by = __ldg(&bias[n + 1]);
#pragma unroll
        for (int mi = 0; mi < 4; mi++) {
            int r = rw + mi * 16 + (lane >> 2);
            float2 v0 = make_float2(acc[mi][nj][0] + bx, acc[mi][nj][1] + by);
            float2 v1 = make_float2(acc[mi][nj][2] + bx, acc[mi][nj][3] + by);
            *(float2*)(C + (size_t)r * DIM + n)       = v0;
            *(float2*)(C + (size_t)(r + 8) * DIM + n) = v1;
        }
    }
}

// Fused Q/K/V projections: blockIdx.z selects {A, W, bias, C}.
__global__ void __launch_bounds__(256, 1)
gemm_qkv(const float* __restrict__ bq, const float* __restrict__ bk,
         const float* __restrict__ bv) {
    extern __shared__ __align__(1024) char smem[];
    int z = blockIdx.z;
    const __half* A  = (z == 0) ? g_ah : g_ch;
    const __half* B  = (z == 0) ? g_wq : (z == 1) ? g_wk : g_wv;
    const float* bias = (z == 0) ? bq : (z == 1) ? bk : bv;
    float* C          = (z == 0) ? g_q : (z == 1) ? g_k : g_v;
    gemm_body(A, B, bias, C, smem, blockIdx.y * GM, blockIdx.x * GN);
}

// O projection.
__global__ void __launch_bounds__(256, 1)
gemm_o(const float* __restrict__ bo, float* __restrict__ out) {
    extern __shared__ __align__(1024) char smem[];
    gemm_body(g_xh, g_wo, bo, out, smem, blockIdx.y * GM, blockIdx.x * GN);
}

// ---------------------------------------------------------------------------
// Per-token attention: RoPE from global, padded qr/kr, shfl softmax,
// scrambled ctx stored as fp16 for the O projection.
// Scramble: ctx[b,s,h,e] -> row h*128 + s/16, col (s%16)*64 + e
// ---------------------------------------------------------------------------
#define QKPAD 66

__global__ __launch_bounds__(256)
void attn_kernel(float* __restrict__ attn_out, int write_attn) {
    __shared__ float v[DIM];
    __shared__ float qr[HEADS * QKPAD], kr[HEADS * QKPAD];
    __shared__ float sc[256];

    int t   = blockIdx.x;
    int b   = t >> 11;
    int s   = t & (SEQ - 1);
    int tid = threadIdx.x;
    int d   = tid * 4;

    ((float4*)v)[tid] = ((const float4*)(g_v + (size_t)t * DIM))[tid];

    // RoPE directly from global q/k
    {
        int j  = d & (HALF - 1);
        int pd = (d < HALF) ? d + HALF : d - HALF;
        float sgn = (d < HALF) ? -1.0f : 1.0f;
        float4 c4 = *(const float4*)(g_cos + (size_t)s * HALF + j);
        float4 s4 = *(const float4*)(g_sin + (size_t)s * HALF + j);
        const float* qg = g_q + (size_t)t * DIM;
        const float* kg = g_k + (size_t)t * DIM;
        float4 qv = *(const float4*)(qg + d),  qp = *(const float4*)(qg + pd);
        float4 kv = *(const float4*)(kg + d),  kp = *(const float4*)(kg + pd);
        int row = d >> 6, e = d & 63;
        float* qd = qr + row * QKPAD + e;
        float* kd = kr + row * QKPAD + e;
        qd[0] = qv.x * c4.x + sgn * qp.x * s4.x;
        qd[1] = qv.y * c4.y + sgn * qp.y * s4.y;
        qd[2] = qv.z * c4.z + sgn * qp.z * s4.z;
        qd[3] = qv.w * c4.w + sgn * qp.w * s4.w;
        kd[0] = kv.x * c4.x + sgn * kp.x * s4.x;
        kd[1] = kv.y * c4.y + sgn * kp.y * s4.y;
        kd[2] = kv.z * c4.z + sgn * kp.z * s4.z;
        kd[3] = kv.w * c4.w + sgn * kp.w * s4.w;
    }
    __syncthreads();

    // Scores + softmax, one thread per (i,j)
    {
        int i = tid >> 4, j = tid & 15;
        const float* qp = qr + i * QKPAD;
        const float* kp = kr + j * QKPAD;
        float sum = 0.0f;
#pragma unroll
        for (int e = 0; e < HD; e++) sum += qp[e] * kp[e];
        sum *= 0.125f;
        float m = sum;
#pragma unroll
        for (int off = 8; off > 0; off >>= 1)
            m = fmaxf(m, __shfl_xor_sync(0xFFFFFFFFu, m, off, 16));
        float ex = expf(sum - m);
        float tot = ex;
#pragma unroll
        for (int off = 8; off > 0; off >>= 1)
            tot += __shfl_xor_sync(0xFFFFFFFFu, tot, off, 16);
        float p = ex / tot;
        sc[tid] = p;
        if (write_attn) attn_out[(size_t)t * 256 + tid] = p;
    }
    __syncthreads();

    // ctx + scrambled fp16 store
    {
        int i = d >> 6, e = d & 63;
        float4 acc = make_float4(0.f, 0.f, 0.f, 0.f);
        const float* pr = sc + i * 16;
#pragma unroll
        for (int j = 0; j < HEADS; j++) {
            float p = pr[j];
            float4 vv = *(float4*)(v + j * HD + e);
            acc.x += p * vv.x; acc.y += p * vv.y;
            acc.z += p * vv.z; acc.w += p * vv.w;
        }
        int r = i * (SEQ / HEADS) + (s >> 4);
        int c = ((s & 15) << 6) | e;
        size_t off = (size_t)b * SEQ * DIM + (size_t)r * DIM + c;
        *(__half2*)(g_xh + off)     = __floats2half2_rn(acc.x, acc.y);
        *(__half2*)(g_xh + off + 2) = __floats2half2_rn(acc.z, acc.w);
    }
}

// ---------------------------------------------------------------------------
// Host launcher. Launch #4 == gemm_qkv  <-- ncu capture slot.
// ---------------------------------------------------------------------------
extern "C" void kernel_launch(void* const* d_in, const int* in_sizes, int n_in,
                              void* d_out, int out_size) {
    const float* inputs  = (const float*)d_in[0];
    const float* context = (const float*)d_in[1];
    const float* Wq = (const float*)d_in[2];
    const float* bq = (const float*)d_in[3];
    const float* Wk = (const float*)d_in[4];
    const float* bk = (const float*)d_in[5];
    const float* Wv = (const float*)d_in[6];
    const float* bv = (const float*)d_in[7];
    const float* Wo = (const float*)d_in[8];
    const float* bo = (const float*)d_in[9];
    float* out = (float*)d_out;

    cudaFuncSetAttribute(gemm_qkv, cudaFuncAttributeMaxDynamicSharedMemorySize,
                         SMEM_TOTAL);
    cudaFuncSetAttribute(gemm_o, cudaFuncAttributeMaxDynamicSharedMemorySize,
                         SMEM_TOTAL);

    __half *pah, *pch;
    cudaGetSymbolAddress((void**)&pah, g_ah);
    cudaGetSymbolAddress((void**)&pch, g_ch);

    const int out_elems  = MTOK * DIM;
    const int attn_elems = MTOK * HEADS * HEADS;
    int write_attn = (out_size >= out_elems + attn_elems) ? 1 : 0;
    float* attn_out = out + out_elems;

    // #1: weight transposes (one launch)
    convert_w4_kernel<<<dim3(32, 32, 4), dim3(32, 8)>>>(Wq, Wk, Wv, Wo);
    // #2-3: activation fp16 conversion
    act_half_kernel<<<(MTOK * DIM) / 1024, 256>>>(inputs,  pah);
    act_half_kernel<<<(MTOK * DIM) / 1024, 256>>>(context, pch);
    // #4: fused Q/K/V projections  <-- ncu capture slot
    gemm_qkv<<<dim3(DIM / GN, MTOK / GM, 3), 256, SMEM_TOTAL>>>(bq, bk, bv);
    // #5: RoPE tables
    rope_tab_kernel<<<(SEQ * HALF) / 256, 256>>>();
    // #6: RoPE + per-token head attention + scramble (fp16 ctx out)
    attn_kernel<<<MTOK, 256>>>(attn_out, write_attn);
    // #7: O projection
    gemm_o<<<dim3(DIM / GN, MTOK / GM), 256, SMEM_TOTAL>>>(bo, out);
}

// round 16
// speedup vs baseline: 1.8035x; 1.1942x over previous
#include <cuda_runtime.h>
#include <cuda_fp16.h>
#include <stdint.h>
#include <math.h>

// Problem constants
#define BATCH 2
#define SEQ   2048
#define DIM   1024
#define HEADS 16
#define HD    64
#define MTOK  (BATCH * SEQ)            // 4096 tokens
#define HALF  (DIM / 2)                // 512

// fp16 GEMM: CTA 128x256, 8 warps (2Mx4N), warp 64x64, K-chunk 32 halves,
// 4 stages, operands delivered by cp.async.bulk from chunked pre-swizzled gmem.
#define GM 128
#define GN 256
#define GKC 32
#define NCHUNK (DIM / GKC)             // 32
#define NSTAGE 4
#define RA 0
#define RB 8192                         // A tile 128*64B
#define STAGE_BYTES 24576               // + B tile 256*64B
#define SMEM_HDR 1024                   // mbarriers
#define SMEM_TOTAL (SMEM_HDR + NSTAGE * STAGE_BYTES)  // 99328
#define ACHUNK ((size_t)MTOK * 32)      // halves per chunk slab (activations)
#define BCHUNK ((size_t)DIM * 32)       // halves per chunk slab (weights)

// ---------------------------------------------------------------------------
// Device scratch (no cudaMalloc allowed)
// ---------------------------------------------------------------------------
__device__ float g_q[MTOK * DIM];
__device__ float g_k[MTOK * DIM];
__device__ float g_v[MTOK * DIM];
__device__ float g_cos[SEQ * HALF];
__device__ float g_sin[SEQ * HALF];

// Chunked + pre-swizzled fp16 operands: [chunk][row][16 words of 2 halves]
// physical word p = (w + 4*((row>>1)&3)) & 15
__device__ __half g_ah[MTOK * DIM];      // fp16(inputs)
__device__ __half g_ch[MTOK * DIM];      // fp16(context)
__device__ __half g_xh[MTOK * DIM];      // fp16(scrambled ctx)
__device__ __half g_wq[DIM * DIM];       // transposed [N][K] weights
__device__ __half g_wk[DIM * DIM];
__device__ __half g_wv[DIM * DIM];
__device__ __half g_wo[DIM * DIM];

// ---------------------------------------------------------------------------
// Helpers
// ---------------------------------------------------------------------------
__device__ __forceinline__ uint32_t smem_u32(const void* p) {
    uint32_t a;
    asm("{ .reg .u64 t; cvta.to.shared.u64 t, %1; cvt.u32.u64 %0, t; }"
        : "=r"(a) : "l"(p));
    return a;
}

__device__ __forceinline__ void mbar_init(uint32_t a, uint32_t cnt) {
    asm volatile("mbarrier.init.shared.b64 [%0], %1;" :: "r"(a), "r"(cnt) : "memory");
}
__device__ __forceinline__ void mbar_expect(uint32_t a, uint32_t bytes) {
    asm volatile("mbarrier.arrive.expect_tx.shared.b64 _, [%0], %1;"
                 :: "r"(a), "r"(bytes) : "memory");
}
__device__ __forceinline__ void mbar_wait(uint32_t a, uint32_t parity) {
    asm volatile(
        "{\n\t.reg .pred P;\n"
        "W%=:\n\t"
        "mbarrier.try_wait.parity.shared.b64 P, [%0], %1;\n\t"
        "@P bra D%=;\n\t"
        "bra W%=;\n"
        "D%=:\n\t}"
        :: "r"(a), "r"(parity) : "memory");
}
__device__ __forceinline__ void cpbulk(uint32_t dst, const void* src,
                                       uint32_t bytes, uint32_t mbar) {
    asm volatile(
        "cp.async.bulk.shared::cta.global.mbarrier::complete_tx::bytes "
        "[%0], [%1], %2, [%3];"
        :: "r"(dst), "l"(src), "r"(bytes), "r"(mbar) : "memory");
}

__device__ __forceinline__ uint32_t lds_u32(uint32_t addr) {
    uint32_t v;
    asm volatile("ld.shared.b32 %0, [%1];" : "=r"(v) : "r"(addr));
    return v;
}

// fp16 mma, fp32 accumulate: m16n8k16
__device__ __forceinline__ void mma_f16(float* d, const uint32_t* a,
                                        uint32_t b0, uint32_t b1) {
    asm volatile(
        "mma.sync.aligned.m16n8k16.row.col.f32.f16.f16.f32 "
        "{%0,%1,%2,%3}, {%4,%5,%6,%7}, {%8,%9}, {%0,%1,%2,%3};"
        : "+f"(d[0]), "+f"(d[1]), "+f"(d[2]), "+f"(d[3])
        : "r"(a[0]), "r"(a[1]), "r"(a[2]), "r"(a[3]), "r"(b0), "r"(b1));
}

// ---------------------------------------------------------------------------
// RoPE tables — fp32 throughout.
// ---------------------------------------------------------------------------
__global__ void rope_tab_kernel() {
    int idx = blockIdx.x * 256 + threadIdx.x;
    int s = idx >> 9;
    int j = idx & (HALF - 1);
    float inv = exp2f((float)j * -0.025952563241303614f);  // 2*log2(1e4)/1024
    float arg = (float)s * inv;
    float sn, cs;
    sincosf(arg, &sn, &cs);
    g_cos[idx] = cs;
    g_sin[idx] = sn;
}

// ---------------------------------------------------------------------------
// Activations: fp32 -> fp16, chunked pre-swizzled layout.
// ---------------------------------------------------------------------------
__global__ void act_half_kernel(const float* __restrict__ X,
                                __half* __restrict__ Y) {
    int i = (blockIdx.x * 256 + threadIdx.x) * 4;
    float4 x = *(const float4*)(X + i);
    int row   = i >> 10;
    int col   = i & 1023;                // half index within row, multiple of 4
    int chunk = col >> 5;
    int w     = (col & 31) >> 1;         // even logical word, <= 14
    int p     = (w + 4 * ((row >> 1) & 3)) & 15;
    size_t base = ((size_t)chunk * MTOK + row) * 32 + p * 2;
    *(__half2*)(Y + base)     = __floats2half2_rn(x.x, x.y);
    *(__half2*)(Y + base + 2) = __floats2half2_rn(x.z, x.w);
}

// ---------------------------------------------------------------------------
// Weight transposes: W [K][N] fp32 -> chunked pre-swizzled fp16 [N][K].
// blockIdx.z selects the matrix.
// ---------------------------------------------------------------------------
__global__ void convert_w4_kernel(const float* __restrict__ W0,
                                  const float* __restrict__ W1,
                                  const float* __restrict__ W2,
                                  const float* __restrict__ W3) {
    __shared__ float t[32][33];
    const float* W = (blockIdx.z == 0) ? W0 : (blockIdx.z == 1) ? W1
                   : (blockIdx.z == 2) ? W2 : W3;
    __half* T = (blockIdx.z == 0) ? g_wq : (blockIdx.z == 1) ? g_wk
              : (blockIdx.z == 2) ? g_wv : g_wo;
    int k0 = blockIdx.y * 32, n0 = blockIdx.x * 32;
    int tx = threadIdx.x, ty = threadIdx.y;   // 32 x 8
#pragma unroll
    for (int i = 0; i < 32; i += 8)
        t[ty + i][tx] = W[(size_t)(k0 + ty + i) * DIM + n0 + tx];
    __syncthreads();
#pragma unroll
    for (int i = 0; i < 32; i += 8) {
        float x = t[tx][ty + i];              // W[k0+tx][n0+ty+i]
        int n = n0 + ty + i;
        int k = k0 + tx;
        int chunk = k >> 5;
        int w = (k & 31) >> 1;
        int p = (w + 4 * ((n >> 1) & 3)) & 15;
        T[((size_t)chunk * DIM + n) * 32 + p * 2 + (k & 1)] = __float2half_rn(x);
    }
}

// ---------------------------------------------------------------------------
// fp16 single-product GEMM with cp.async.bulk operand delivery.
// C[M,N] = A @ B^T + bias (fp32 accumulate). Per chunk: 2 bulk copies
// (8KB A + 16KB B) into a 4-stage mbarrier pipeline — zero LDGSTS issue cost.
// ---------------------------------------------------------------------------
__device__ __forceinline__ void gemm_body(
    const __half* __restrict__ A, const __half* __restrict__ B,
    const float* __restrict__ bias, float* __restrict__ C,
    char* smem, int row0, int col0) {
    const int tid  = threadIdx.x;
    const int wid  = tid >> 5;
    const int lane = tid & 31;
    const uint32_t sb = smem_u32(smem);

    const int wm = wid >> 2;            // 0..1
    const int wn = wid & 3;             // 0..3
    const int m_base = wm * 64;
    const int n_base = wn * 64;

    // mbarriers: one per stage
    if (tid == 0) {
#pragma unroll
        for (int s = 0; s < NSTAGE; s++) mbar_init(sb + s * 8, 1);
    }
    __syncthreads();

    auto produce = [&](int c) {
        const int st = c & (NSTAGE - 1);
        const uint32_t stg = sb + SMEM_HDR + (uint32_t)st * STAGE_BYTES;
        const uint32_t mb  = sb + st * 8;
        mbar_expect(mb, STAGE_BYTES);
        cpbulk(stg + RA, A + (size_t)c * ACHUNK + (size_t)row0 * 32, 8192, mb);
        cpbulk(stg + RB, B + (size_t)c * BCHUNK + (size_t)col0 * 32, 16384, mb);
    };

    if (tid == 0) { produce(0); produce(1); produce(2); }

    // physical word offsets (pre-swizzled layout): p = (w + 4*((r>>1)&3)) & 15
    const int pw = (lane & 3) + 4 * ((lane >> 3) & 3);
    const uint32_t w_ks[2][2] = {
        { (uint32_t)((pw)      & 15) * 4, (uint32_t)((pw + 4)  & 15) * 4 },
        { (uint32_t)((pw + 8)  & 15) * 4, (uint32_t)((pw + 12) & 15) * 4 } };

    float acc[4][8][4];
#pragma unroll
    for (int i = 0; i < 4; i++)
#pragma unroll
        for (int j = 0; j < 8; j++)
#pragma unroll
            for (int e = 0; e < 4; e++) acc[i][j][e] = 0.0f;

    for (int c = 0; c < NCHUNK; c++) {
        const int st = c & (NSTAGE - 1);
        mbar_wait(sb + st * 8, (uint32_t)((c >> 2) & 1));
        __syncthreads();
        // stage (c+3)%4 == (c-1)%4: all readers passed the barrier above.
        if (tid == 0 && c + 3 < NCHUNK) produce(c + 3);

        const uint32_t stg = sb + SMEM_HDR + (uint32_t)st * STAGE_BYTES;
        const uint32_t abase = stg + RA + (m_base + (lane >> 2)) * 64;
        const uint32_t bbase = stg + RB + (n_base + (lane >> 2)) * 64;

        uint32_t af[2][4][4], bf[2][8][2];

        auto load_frags = [&](int ks, int buf) {
            const uint32_t wa = w_ks[ks][0], wb = w_ks[ks][1];
#pragma unroll
            for (int mi = 0; mi < 4; mi++) {
                uint32_t base = abase + mi * 1024;
                af[buf][mi][0] = lds_u32(base + wa);
                af[buf][mi][1] = lds_u32(base + 512 + wa);
                af[buf][mi][2] = lds_u32(base + wb);
                af[buf][mi][3] = lds_u32(base + 512 + wb);
            }
#pragma unroll
            for (int nj = 0; nj < 8; nj++) {
                uint32_t base = bbase + nj * 512;
                bf[buf][nj][0] = lds_u32(base + wa);
                bf[buf][nj][1] = lds_u32(base + wb);
            }
        };

        load_frags(0, 0);
#pragma unroll
        for (int ks = 0; ks < 2; ks++) {
            if (ks < 1) load_frags(ks + 1, (ks + 1) & 1);
            const int cb = ks & 1;
#pragma unroll
            for (int mi = 0; mi < 4; mi++)
#pragma unroll
                for (int nj = 0; nj < 8; nj++)
                    mma_f16(acc[mi][nj], af[cb][mi], bf[cb][nj][0], bf[cb][nj][1]);
        }
    }

    // Epilogue: add bias, store fp32
    const int rw = row0 + m_base;
    const int cw = col0 + n_base;
#pragma unroll
    for (int nj = 0; nj < 8; nj++) {
        int n = cw + nj * 8 + (lane & 3) * 2;
        float bx = __ldg(&bias[n]);
        float by = __ldg(&bias[n + 1]);
#pragma unroll
        for (int mi = 0; mi < 4; mi++) {
            int r = rw + mi * 16 + (lane >> 2);
            float2 v0 = make_float2(acc[mi][nj][0] + bx, acc[mi][nj][1] + by);
            float2 v1 = make_float2(acc[mi][nj][2] + bx, acc[mi][nj][3] + by);
            *(float2*)(C + (size_t)r * DIM + n)       = v0;
            *(float2*)(C + (size_t)(r + 8) * DIM + n) = v1;
        }
    }
}

// Fused Q/K/V projections: blockIdx.z selects {A, W, bias, C}.
__global__ void __launch_bounds__(256, 1)
gemm_qkv(const float* __restrict__ bq, const float* __restrict__ bk,
         const float* __restrict__ bv) {
    extern __shared__ __align__(1024) char smem[];
    int z = blockIdx.z;
    const __half* A  = (z == 0) ? g_ah : g_ch;
    const __half* B  = (z == 0) ? g_wq : (z == 1) ? g_wk : g_wv;
    const float* bias = (z == 0) ? bq : (z == 1) ? bk : bv;
    float* C          = (z == 0) ? g_q : (z == 1) ? g_k : g_v;
    gemm_body(A, B, bias, C, smem, blockIdx.y * GM, blockIdx.x * GN);
}

// O projection.
__global__ void __launch_bounds__(256, 1)
gemm_o(const float* __restrict__ bo, float* __restrict__ out) {
    extern __shared__ __align__(1024) char smem[];
    gemm_body(g_xh, g_wo, bo, out, smem, blockIdx.y * GM, blockIdx.x * GN);
}

// ---------------------------------------------------------------------------
// Per-token attention: RoPE from global, padded qr/kr, shfl softmax,
// scrambled ctx stored as fp16 in the chunked pre-swizzled layout.
// Scramble: ctx[b,s,h,e] -> row h*128 + s/16, col (s%16)*64 + e
// ---------------------------------------------------------------------------
#define QKPAD 66

__global__ __launch_bounds__(256)
void attn_kernel(float* __restrict__ attn_out, int write_attn) {
    __shared__ float v[DIM];
    __shared__ float qr[HEADS * QKPAD], kr[HEADS * QKPAD];
    __shared__ float sc[256];

    int t   = blockIdx.x;
    int b   = t >> 11;
    int s   = t & (SEQ - 1);
    int tid = threadIdx.x;
    int d   = tid * 4;

    ((float4*)v)[tid] = ((const float4*)(g_v + (size_t)t * DIM))[tid];

    // RoPE directly from global q/k
    {
        int j  = d & (HALF - 1);
        int pd = (d < HALF) ? d + HALF : d - HALF;
        float sgn = (d < HALF) ? -1.0f : 1.0f;
        float4 c4 = *(const float4*)(g_cos + (size_t)s * HALF + j);
        float4 s4 = *(const float4*)(g_sin + (size_t)s * HALF + j);
        const float* qg = g_q + (size_t)t * DIM;
        const float* kg = g_k + (size_t)t * DIM;
        float4 qv = *(const float4*)(qg + d),  qp = *(const float4*)(qg + pd);
        float4 kv = *(const float4*)(kg + d),  kp = *(const float4*)(kg + pd);
        int row = d >> 6, e = d & 63;
        float* qd = qr + row * QKPAD + e;
        float* kd = kr + row * QKPAD + e;
        qd[0] = qv.x * c4.x + sgn * qp.x * s4.x;
        qd[1] = qv.y * c4.y + sgn * qp.y * s4.y;
        qd[2] = qv.z * c4.z + sgn * qp.z * s4.z;
        qd[3] = qv.w * c4.w + sgn * qp.w * s4.w;
        kd[0] = kv.x * c4.x + sgn * kp.x * s4.x;
        kd[1] = kv.y * c4.y + sgn * kp.y * s4.y;
        kd[2] = kv.z * c4.z + sgn * kp.z * s4.z;
        kd[3] = kv.w * c4.w + sgn * kp.w * s4.w;
    }
    __syncthreads();

    // Scores + softmax, one thread per (i,j)
    {
        int i = tid >> 4, j = tid & 15;
        const float* qp = qr + i * QKPAD;
        const float* kp = kr + j * QKPAD;
        float sum = 0.0f;
#pragma unroll
        for (int e = 0; e < HD; e++) sum += qp[e] * kp[e];
        sum *= 0.125f;
        float m = sum;
#pragma unroll
        for (int off = 8; off > 0; off >>= 1)
            m = fmaxf(m, __shfl_xor_sync(0xFFFFFFFFu, m, off, 16));
        float ex = expf(sum - m);
        float tot = ex;
#pragma unroll
        for (int off = 8; off > 0; off >>= 1)
            tot += __shfl_xor_sync(0xFFFFFFFFu, tot, off, 16);
        float p = ex / tot;
        sc[tid] = p;
        if (write_attn) attn_out[(size_t)t * 256 + tid] = p;
    }
    __syncthreads();

    // ctx + scrambled chunked-swizzled fp16 store
    {
        int i = d >> 6, e = d & 63;
        float4 acc = make_float4(0.f, 0.f, 0.f, 0.f);
        const float* pr = sc + i * 16;
#pragma unroll
        for (int j = 0; j < HEADS; j++) {
            float p = pr[j];
            float4 vv = *(float4*)(v + j * HD + e);
            acc.x += p * vv.x; acc.y += p * vv.y;
            acc.z += p * vv.z; acc.w += p * vv.w;
        }
        int r = i * (SEQ / HEADS) + (s >> 4);
        int c = ((s & 15) << 6) | e;
        int R = b * SEQ + r;                 // global row in [0, 4096)
        int chunk = c >> 5;
        int w = (c & 31) >> 1;               // even, <= 14
        int p = (w + 4 * ((R >> 1) & 3)) & 15;
        size_t base = ((size_t)chunk * MTOK + R) * 32 + p * 2;
        *(__half2*)(g_xh + base)     = __floats2half2_rn(acc.x, acc.y);
        *(__half2*)(g_xh + base + 2) = __floats2half2_rn(acc.z, acc.w);
    }
}

// ---------------------------------------------------------------------------
// Host launcher. Launch #4 == gemm_qkv  <-- ncu capture slot.
// ---------------------------------------------------------------------------
extern "C" void kernel_launch(void* const* d_in, const int* in_sizes, int n_in,
                              void* d_out, int out_size) {
    const float* inputs  = (const float*)d_in[0];
    const float* context = (const float*)d_in[1];
    const float* Wq = (const float*)d_in[2];
    const float* bq = (const float*)d_in[3];
    const float* Wk = (const float*)d_in[4];
    const float* bk = (const float*)d_in[5];
    const float* Wv = (const float*)d_in[6];
    const float* bv = (const float*)d_in[7];
    const float* Wo = (const float*)d_in[8];
    const float* bo = (const float*)d_in[9];
    float* out = (float*)d_out;

    cudaFuncSetAttribute(gemm_qkv, cudaFuncAttributeMaxDynamicSharedMemorySize,
                         SMEM_TOTAL);
    cudaFuncSetAttribute(gemm_o, cudaFuncAttributeMaxDynamicSharedMemorySize,
                         SMEM_TOTAL);

    __half *pah, *pch;
    cudaGetSymbolAddress((void**)&pah, g_ah);
    cudaGetSymbolAddress((void**)&pch, g_ch);

    const int out_elems  = MTOK * DIM;
    const int attn_elems = MTOK * HEADS * HEADS;
    int write_attn = (out_size >= out_elems + attn_elems) ? 1 : 0;
    float* attn_out = out + out_elems;

    // #1: weight transposes -> chunked swizzled fp16 (one launch)
    convert_w4_kernel<<<dim3(32, 32, 4), dim3(32, 8)>>>(Wq, Wk, Wv, Wo);
    // #2-3: activation fp16 conversion -> chunked swizzled layout
    act_half_kernel<<<(MTOK * DIM) / 1024, 256>>>(inputs,  pah);
    act_half_kernel<<<(MTOK * DIM) / 1024, 256>>>(context, pch);
    // #4: fused Q/K/V projections  <-- ncu capture slot
    gemm_qkv<<<dim3(DIM / GN, MTOK / GM, 3), 256, SMEM_TOTAL>>>(bq, bk, bv);
    // #5: RoPE tables
    rope_tab_kernel<<<(SEQ * HALF) / 256, 256>>>();
    // #6: RoPE + per-token head attention + scramble (chunked fp16 ctx out)
    attn_kernel<<<MTOK, 256>>>(attn_out, write_attn);
    // #7: O projection
    gemm_o<<<dim3(DIM / GN, MTOK / GM), 256, SMEM_TOTAL>>>(bo, out);
}